// round 3
// baseline (speedup 1.0000x reference)
#include <cuda_runtime.h>
#include <cstdint>
#include <math.h>

// Accurate libdevice log (what XLA emits for lax.log on f32) — call directly so
// fast-math can never remap it. Bitwise-identical gumbels => identical argmax.
extern "C" __device__ float __nv_logf(float);

// ---------------------------------------------------------------------------
// Compile-time Threefry-2x32 for deriving split keys.
// Partitionable (fold-like) split: key_i = threefry(parent, (0, i)), both lanes.
// ---------------------------------------------------------------------------
constexpr unsigned crotl(unsigned x, int r) { return (x << r) | (x >> (32 - r)); }
struct CKeys { unsigned a, b; };
constexpr CKeys ctf(unsigned k0, unsigned k1, unsigned x0, unsigned x1) {
    unsigned k2 = k0 ^ k1 ^ 0x1BD11BDAu;
    const int rotA[4] = {13, 15, 26, 6};
    const int rotB[4] = {17, 29, 16, 24};
    x0 += k0; x1 += k1;
    for (int i = 0; i < 4; i++) { x0 += x1; x1 = crotl(x1, rotA[i]); x1 ^= x0; }
    x0 += k1; x1 += k2 + 1u;
    for (int i = 0; i < 4; i++) { x0 += x1; x1 = crotl(x1, rotB[i]); x1 ^= x0; }
    x0 += k2; x1 += k0 + 2u;
    for (int i = 0; i < 4; i++) { x0 += x1; x1 = crotl(x1, rotA[i]); x1 ^= x0; }
    x0 += k0; x1 += k1 + 3u;
    for (int i = 0; i < 4; i++) { x0 += x1; x1 = crotl(x1, rotB[i]); x1 ^= x0; }
    x0 += k1; x1 += k2 + 4u;
    for (int i = 0; i < 4; i++) { x0 += x1; x1 = crotl(x1, rotA[i]); x1 ^= x0; }
    x0 += k2; x1 += k0 + 5u;
    return {x0, x1};
}
// split(key(42), 2) [partitionable / fold-like]:
//   k_cat  = both lanes of threefry((0,42), (0,0))
//   k_bern = both lanes of threefry((0,42), (0,1))
constexpr CKeys KCAT  = ctf(0u, 42u, 0u, 0u);
constexpr CKeys KBERN = ctf(0u, 42u, 0u, 1u);

// ---------------------------------------------------------------------------
// Device Threefry-2x32. Partitionable random_bits (32-bit) returns
// lane0 ^ lane1 of threefry(key, (hi(j), lo(j))). All sizes < 2^32 => hi = 0.
// ---------------------------------------------------------------------------
__device__ __forceinline__ unsigned rotl(unsigned x, int r) {
    return __funnelshift_l(x, x, r);
}

__device__ __forceinline__ unsigned tf_bits32(unsigned k0, unsigned k1, unsigned x1) {
    unsigned k2 = k0 ^ k1 ^ 0x1BD11BDAu;
    unsigned x0 = k0;          // x0 starts at 0 + k0
    x1 += k1;
#define TFR(r) { x0 += x1; x1 = rotl(x1, r); x1 ^= x0; }
    TFR(13) TFR(15) TFR(26) TFR(6)
    x0 += k1; x1 += k2 + 1u;
    TFR(17) TFR(29) TFR(16) TFR(24)
    x0 += k2; x1 += k0 + 2u;
    TFR(13) TFR(15) TFR(26) TFR(6)
    x0 += k0; x1 += k1 + 3u;
    TFR(17) TFR(29) TFR(16) TFR(24)
    x0 += k1; x1 += k2 + 4u;
    TFR(13) TFR(15) TFR(26) TFR(6)
#undef TFR
    // lane0 = x0 + k2, lane1 = x1 + k0 + 5; 32-bit partitionable bits = XOR
    return (x0 + k2) ^ (x1 + k0 + 5u);
}

// JAX uniform [0,1): bitcast((bits>>9)|0x3f800000) - 1
__device__ __forceinline__ float u01f(unsigned bits) {
    return __uint_as_float((bits >> 9) | 0x3f800000u) - 1.0f;
}

// JAX gumbel: -log(-log(uniform(minval=tiny, maxval=1)))
__device__ __forceinline__ float gumbelf(unsigned bits) {
    float u = fmaxf(u01f(bits), 1.17549435e-38f);
    return -__nv_logf(-__nv_logf(u));
}

// ---------------------------------------------------------------------------
// One thread per 8x8 window. 64 threefry draws for gumbel-argmax, 1 draw for
// the bernoulli. No shuffles, no divergence.
// Windows: w = b*65536 + hc*256 + wc, b in 0..7. Gumbel counter = w*64 + k.
// ---------------------------------------------------------------------------
__global__ __launch_bounds__(256)
void keypoint_sampler_kernel(const float* __restrict__ x, float* __restrict__ out) {
    const unsigned w = blockIdx.x * 256u + threadIdx.x;   // 0 .. 524287

    const unsigned b  = w >> 16;
    const unsigned hc = (w >> 8) & 255u;
    const unsigned wc = w & 255u;

    const float* base = x + ((size_t)b << 22) + (size_t)(hc * 8u) * 2048u + wc * 8u;

    float best = -3.4e38f;
    int   bi   = 0;
    float sel  = 0.0f;
    float esum = 0.0f;

    const unsigned cbase = w * 64u;

#pragma unroll 1
    for (int r = 0; r < 8; r++) {
        const float4 p0 = *(const float4*)(base + (size_t)r * 2048u);
        const float4 p1 = *(const float4*)(base + (size_t)r * 2048u + 4u);
        float v[8] = {p0.x, p0.y, p0.z, p0.w, p1.x, p1.y, p1.z, p1.w};

        const unsigned c = cbase + (unsigned)r * 8u;
#pragma unroll
        for (int i = 0; i < 8; i++) {
            const unsigned gb = tf_bits32(KCAT.a, KCAT.b, c + (unsigned)i);
            const float s = v[i] + gumbelf(gb);
            esum += __expf(v[i]);
            if (s > best) { best = s; bi = r * 8 + i; sel = v[i]; }
        }
    }

    // Bernoulli: uniform bits for element w
    const float u = u01f(tf_bits32(KBERN.a, KBERN.b, w));

    // correctly-rounded f32 sigmoid via double (boundary fidelity vs XLA)
    const double sig = 1.0 / (1.0 + exp(-(double)sel));
    const bool acc = u < (float)sig;

    // log-probs (continuous outputs, 1e-3 tolerance)
    const float e       = __expf(-fabsf(sel));
    const float lse     = log1pf(e);
    const float bern_lp = (acc ? fminf(sel, 0.0f) : fminf(-sel, 0.0f)) - lse;
    const float cat_lp  = sel - __nv_logf(esum);

    const int ddi = bi >> 3, ddj = bi & 7;

    // tuple layout: kp_xy [2*524288] | log_probs [524288] | mask [524288]
    ((float2*)out)[w]  = make_float2((float)(wc * 8u + (unsigned)ddj),   // x=col
                                     (float)(hc * 8u + (unsigned)ddi)); // y=row
    out[1048576u + w]  = cat_lp + bern_lp;
    out[1572864u + w]  = acc ? 1.0f : 0.0f;
}

extern "C" void kernel_launch(void* const* d_in, const int* in_sizes, int n_in,
                              void* d_out, int out_size) {
    const float* x = (const float*)d_in[0];
    float* out = (float*)d_out;
    keypoint_sampler_kernel<<<2048, 256>>>(x, out);
}

// round 4
// speedup vs baseline: 1.0275x; 1.0275x over previous
#include <cuda_runtime.h>
#include <cstdint>
#include <math.h>

// Accurate libdevice log (what XLA emits for lax.log on f32) — call directly so
// fast-math can never remap it. Bitwise-identical gumbels => identical argmax.
extern "C" __device__ float __nv_logf(float);

// ---------------------------------------------------------------------------
// Compile-time Threefry-2x32 for deriving split keys.
// Partitionable (fold-like) split: key_i = threefry(parent, (0, i)), both lanes.
// ---------------------------------------------------------------------------
constexpr unsigned crotl(unsigned x, int r) { return (x << r) | (x >> (32 - r)); }
struct CKeys { unsigned a, b; };
constexpr CKeys ctf(unsigned k0, unsigned k1, unsigned x0, unsigned x1) {
    unsigned k2 = k0 ^ k1 ^ 0x1BD11BDAu;
    const int rotA[4] = {13, 15, 26, 6};
    const int rotB[4] = {17, 29, 16, 24};
    x0 += k0; x1 += k1;
    for (int i = 0; i < 4; i++) { x0 += x1; x1 = crotl(x1, rotA[i]); x1 ^= x0; }
    x0 += k1; x1 += k2 + 1u;
    for (int i = 0; i < 4; i++) { x0 += x1; x1 = crotl(x1, rotB[i]); x1 ^= x0; }
    x0 += k2; x1 += k0 + 2u;
    for (int i = 0; i < 4; i++) { x0 += x1; x1 = crotl(x1, rotA[i]); x1 ^= x0; }
    x0 += k0; x1 += k1 + 3u;
    for (int i = 0; i < 4; i++) { x0 += x1; x1 = crotl(x1, rotB[i]); x1 ^= x0; }
    x0 += k1; x1 += k2 + 4u;
    for (int i = 0; i < 4; i++) { x0 += x1; x1 = crotl(x1, rotA[i]); x1 ^= x0; }
    x0 += k2; x1 += k0 + 5u;
    return {x0, x1};
}
constexpr CKeys KCAT  = ctf(0u, 42u, 0u, 0u);   // k_cat
constexpr CKeys KBERN = ctf(0u, 42u, 0u, 1u);   // k_bern

// ---------------------------------------------------------------------------
// Device Threefry-2x32; partitionable 32-bit random_bits = lane0 ^ lane1,
// counter = (0, j) for flat index j (< 2^32 here).
// ---------------------------------------------------------------------------
__device__ __forceinline__ unsigned rotl(unsigned x, int r) {
    return __funnelshift_l(x, x, r);
}

__device__ __forceinline__ unsigned tf_bits32(unsigned k0, unsigned k1, unsigned x1) {
    unsigned k2 = k0 ^ k1 ^ 0x1BD11BDAu;
    unsigned x0 = k0;
    x1 += k1;
#define TFR(r) { x0 += x1; x1 = rotl(x1, r); x1 ^= x0; }
    TFR(13) TFR(15) TFR(26) TFR(6)
    x0 += k1; x1 += k2 + 1u;
    TFR(17) TFR(29) TFR(16) TFR(24)
    x0 += k2; x1 += k0 + 2u;
    TFR(13) TFR(15) TFR(26) TFR(6)
    x0 += k0; x1 += k1 + 3u;
    TFR(17) TFR(29) TFR(16) TFR(24)
    x0 += k1; x1 += k2 + 4u;
    TFR(13) TFR(15) TFR(26) TFR(6)
#undef TFR
    return (x0 + k2) ^ (x1 + k0 + 5u);
}

// JAX uniform [0,1): bitcast((bits>>9)|0x3f800000) - 1
__device__ __forceinline__ float u01f(unsigned bits) {
    return __uint_as_float((bits >> 9) | 0x3f800000u) - 1.0f;
}

// ---------------------------------------------------------------------------
// One thread per 8x8 window. 64 threefry draws (gumbel) + 1 (bernoulli).
// ---------------------------------------------------------------------------
__global__ __launch_bounds__(128)
void keypoint_sampler_kernel(const float* __restrict__ x, float* __restrict__ out) {
    const unsigned w = blockIdx.x * 128u + threadIdx.x;   // 0 .. 524287

    const unsigned b  = w >> 16;
    const unsigned hc = (w >> 8) & 255u;
    const unsigned wc = w & 255u;

    const float* base = x + ((size_t)b << 22) + (size_t)(hc * 8u) * 2048u + wc * 8u;

    // Bernoulli bits early (independent ILP, overlaps first loads)
    const unsigned bbits = tf_bits32(KBERN.a, KBERN.b, w);

    float best = -3.4e38f;
    int   bi   = 0;
    float esum = 0.0f;

    const unsigned cbase = w * 64u;

#pragma unroll 1
    for (int r = 0; r < 8; r++) {
        const float4 p0 = *(const float4*)(base + (size_t)r * 2048u);
        const float4 p1 = *(const float4*)(base + (size_t)r * 2048u + 4u);
        float v[8] = {p0.x, p0.y, p0.z, p0.w, p1.x, p1.y, p1.z, p1.w};

        const unsigned c = cbase + (unsigned)r * 8u;
#pragma unroll
        for (int i = 0; i < 8; i++) {
            const unsigned gb = tf_bits32(KCAT.a, KCAT.b, c + (unsigned)i);
            const float u = fmaxf(u01f(gb), 1.17549435e-38f);
            const float t = -__nv_logf(u);
            const float s = v[i] - __nv_logf(t);   // v + gumbel, neg folded into FADD
            esum += __expf(v[i]);
            if (s > best) { best = s; bi = r * 8 + i; }
        }
    }

    // Recover selected grid value with one cached load (cheaper than 64 selects)
    const float sel = __ldg(base + (size_t)(bi >> 3) * 2048u + (unsigned)(bi & 7));

    const float u = u01f(bbits);

    // Fast f32 sigmoid decides unless u is within 2e-3 of it; ambiguous cases
    // (~0.1% of threads) fall back to the correctly-rounded double sigmoid.
    // Decision is identical to always using the double path.
    const float e    = __expf(-fabsf(sel));
    const float rr   = __fdividef(1.0f, 1.0f + e);
    const float sigf = (sel >= 0.0f) ? rr : 1.0f - rr;
    const float du   = u - sigf;
    bool acc;
    if (fabsf(du) > 2e-3f) {
        acc = du < 0.0f;
    } else {
        const double sig = 1.0 / (1.0 + exp(-(double)sel));
        acc = u < (float)sig;
    }

    const float lse     = log1pf(e);
    const float bern_lp = (acc ? fminf(sel, 0.0f) : fminf(-sel, 0.0f)) - lse;
    const float cat_lp  = sel - __nv_logf(esum);

    const int ddi = bi >> 3, ddj = bi & 7;

    // tuple layout: kp_xy [2*524288] | log_probs [524288] | mask [524288]
    ((float2*)out)[w]  = make_float2((float)(wc * 8u + (unsigned)ddj),   // x=col
                                     (float)(hc * 8u + (unsigned)ddi)); // y=row
    out[1048576u + w]  = cat_lp + bern_lp;
    out[1572864u + w]  = acc ? 1.0f : 0.0f;
}

extern "C" void kernel_launch(void* const* d_in, const int* in_sizes, int n_in,
                              void* d_out, int out_size) {
    const float* x = (const float*)d_in[0];
    float* out = (float*)d_out;
    keypoint_sampler_kernel<<<4096, 128>>>(x, out);
}